// round 3
// baseline (speedup 1.0000x reference)
#include <cuda_runtime.h>
#include <math.h>
#include <stdint.h>

#define BSZ   2
#define TLEN  2048
#define DM    1024
#define DI    2048
#define DS    16
#define DTR   64
#define BT    4096     // BSZ*TLEN
#define XDBW  96       // DTR + 2*DS

// ---------------- scratch (device globals; no allocation allowed) ----------
__device__ float g_tmp[BT * DM];                 // x @ W_delta
__device__ float g_xg [BT * DM];                 // gated x
__device__ float g_xz [2][BT * (2 * DI)];        // per-dir [xi | z]
__device__ float g_xc [2][BT * DI];              // conv+silu output
__device__ float g_xdb[2][BT * XDBW];            // [dt_lo | B | C]
__device__ float g_dt [2][BT * DI];              // softplus(dt)
__device__ float g_y  [2][BT * DI];              // scan output (gated)

// ---------------- helpers --------------------------------------------------
__device__ __forceinline__ float softplusf(float v) {
    return v > 20.f ? v : log1pf(expf(v));
}
__device__ __forceinline__ float siluf(float v) {
    return v / (1.f + __expf(-v));
}

// ---------------- generic SGEMM: C = A(MxK) @ B(KxN) (+epilogue) -----------
// flags: 1=flip A rows (within T), 2=flip C rows, 4=accumulate into C,
//        8=add bias[n], 16=softplus
#define F_FLIPA 1
#define F_FLIPC 2
#define F_ACC   4
#define F_BIAS  8
#define F_SP    16

__global__ __launch_bounds__(256, 2)
void sgemm(const float* __restrict__ A, const float* __restrict__ B,
           float* __restrict__ C, const float* __restrict__ bias,
           int M, int N, int K, int lda, int ldb, int ldc, int flags)
{
    __shared__ float As[8][128];
    __shared__ float Bs[8][128];

    const int tid = threadIdx.x;
    const int bm  = blockIdx.y * 128;
    const int bn  = blockIdx.x * 128;

    const int aRow = tid >> 1;          // 0..127
    const int aCol = (tid & 1) * 4;     // 0 or 4
    const int bRow = tid >> 5;          // 0..7
    const int bCol = (tid & 31) * 4;    // 0..124

    int arow_g = bm + aRow;
    int arow_p = arow_g;
    if (flags & F_FLIPA) {
        int b_ = arow_g / TLEN, t_ = arow_g % TLEN;
        arow_p = b_ * TLEN + (TLEN - 1 - t_);
    }
    if (arow_p >= M) arow_p = 0;        // safety (all M are multiples of 128)
    const float* Aptr = A + (size_t)arow_p * lda + aCol;

    const int tr = (tid >> 4) * 8;
    const int tc = (tid & 15) * 8;

    float acc[8][8];
#pragma unroll
    for (int i = 0; i < 8; i++)
#pragma unroll
        for (int j = 0; j < 8; j++) acc[i][j] = 0.f;

    for (int k0 = 0; k0 < K; k0 += 8) {
        float4 a4 = *(const float4*)(Aptr + k0);
        As[aCol + 0][aRow] = a4.x;
        As[aCol + 1][aRow] = a4.y;
        As[aCol + 2][aRow] = a4.z;
        As[aCol + 3][aRow] = a4.w;

        float4 b4 = make_float4(0.f, 0.f, 0.f, 0.f);
        int gb = bn + bCol;
        if (gb < N) b4 = *(const float4*)(B + (size_t)(k0 + bRow) * ldb + gb);
        *(float4*)&Bs[bRow][bCol] = b4;

        __syncthreads();
#pragma unroll
        for (int k = 0; k < 8; k++) {
            float ar[8], br[8];
            float4 t0 = *(const float4*)&As[k][tr];
            float4 t1 = *(const float4*)&As[k][tr + 4];
            ar[0]=t0.x; ar[1]=t0.y; ar[2]=t0.z; ar[3]=t0.w;
            ar[4]=t1.x; ar[5]=t1.y; ar[6]=t1.z; ar[7]=t1.w;
            float4 u0 = *(const float4*)&Bs[k][tc];
            float4 u1 = *(const float4*)&Bs[k][tc + 4];
            br[0]=u0.x; br[1]=u0.y; br[2]=u0.z; br[3]=u0.w;
            br[4]=u1.x; br[5]=u1.y; br[6]=u1.z; br[7]=u1.w;
#pragma unroll
            for (int i = 0; i < 8; i++)
#pragma unroll
                for (int j = 0; j < 8; j++)
                    acc[i][j] = fmaf(ar[i], br[j], acc[i][j]);
        }
        __syncthreads();
    }

#pragma unroll
    for (int i = 0; i < 8; i++) {
        int gm = bm + tr + i;
        if (gm >= M) continue;
        int gmp = gm;
        if (flags & F_FLIPC) {
            int b_ = gm / TLEN, t_ = gm % TLEN;
            gmp = b_ * TLEN + (TLEN - 1 - t_);
        }
#pragma unroll
        for (int j = 0; j < 8; j++) {
            int gn = bn + tc + j;
            if (gn >= N) continue;
            float v = acc[i][j];
            size_t ci = (size_t)gmp * ldc + gn;
            if (flags & F_ACC)  v += C[ci];
            if (flags & F_BIAS) v += bias[gn];
            if (flags & F_SP)   v  = softplusf(v);
            C[ci] = v;
        }
    }
}

// ---------------- quality gating: xg = x * gate ----------------------------
__global__ void gate_kernel(const float* __restrict__ x,
                            const float* __restrict__ u,
                            const float* __restrict__ alpha,
                            const float* __restrict__ b_delta)
{
    int idx = blockIdx.x * blockDim.x + threadIdx.x;
    if (idx >= BT * DM) return;
    int r = idx / DM, c = idx % DM;
    float v        = g_tmp[idx] + b_delta[c];
    float draw     = softplusf(v);
    float delta_id = draw * expf(-alpha[0] * u[r]);
    float gate     = delta_id / (1.f + delta_id);
    g_xg[idx] = x[idx] * gate;
}

// ---------------- causal depthwise conv (window 4) + silu ------------------
__global__ void conv_kernel(const float* __restrict__ cw,
                            const float* __restrict__ cb, int dir)
{
    int idx = blockIdx.x * blockDim.x + threadIdx.x;
    if (idx >= BT * DI) return;
    int r = idx / DI, c = idx % DI;
    int t = r % TLEN;
    const float* xzp = g_xz[dir];
    float acc = cb[c];
#pragma unroll
    for (int k = 0; k < 4; k++) {
        int ts = t - 3 + k;
        if (ts >= 0)
            acc = fmaf(cw[c * 4 + k], xzp[(size_t)(r - 3 + k) * (2 * DI) + c], acc);
    }
    g_xc[dir][idx] = acc / (1.f + __expf(-acc));  // silu
}

// ---------------- selective scan: both dirs, thread per (dir,b,channel) ----
__global__ void scan_kernel(const float* __restrict__ Af,
                            const float* __restrict__ Dpf,
                            const float* __restrict__ Ab,
                            const float* __restrict__ Dpb)
{
    const int dir = blockIdx.z;
    const int b   = blockIdx.y;
    const int d   = blockIdx.x * blockDim.x + threadIdx.x;  // 0..DI-1

    const float* Alog = dir ? Ab  : Af;
    const float* Dp   = dir ? Dpb : Dpf;

    float a[DS], h[DS];
#pragma unroll
    for (int s = 0; s < DS; s++) {
        a[s] = -expf(Alog[d * DS + s]);
        h[s] = 0.f;
    }
    const float dpv = Dp[d];

    const float* dtp  = g_dt[dir];
    const float* xcp  = g_xc[dir];
    const float* xzp  = g_xz[dir];
    const float* xdbp = g_xdb[dir];
    float*       yp   = g_y[dir];

    for (int t = 0; t < TLEN; t++) {
        int    r    = b * TLEN + t;
        size_t base = (size_t)r * DI + d;
        float dtv = dtp[base];
        float xcv = xcp[base];
        float zv  = xzp[(size_t)r * (2 * DI) + DI + d];

        float Bv[DS], Cv[DS];
        const float4* bp4 = (const float4*)(xdbp + (size_t)r * XDBW + DTR);
        const float4* cp4 = (const float4*)(xdbp + (size_t)r * XDBW + DTR + DS);
#pragma unroll
        for (int q = 0; q < 4; q++) {
            float4 bb = __ldg(bp4 + q);
            float4 cc = __ldg(cp4 + q);
            Bv[q*4+0]=bb.x; Bv[q*4+1]=bb.y; Bv[q*4+2]=bb.z; Bv[q*4+3]=bb.w;
            Cv[q*4+0]=cc.x; Cv[q*4+1]=cc.y; Cv[q*4+2]=cc.z; Cv[q*4+3]=cc.w;
        }

        float dtx  = dtv * xcv;
        float ysum = 0.f;
#pragma unroll
        for (int s = 0; s < DS; s++) {
            float dA = __expf(dtv * a[s]);
            h[s] = fmaf(dA, h[s], dtx * Bv[s]);
            ysum = fmaf(h[s], Cv[s], ysum);
        }
        float sz = zv / (1.f + __expf(-zv));     // silu(z)
        yp[base] = (ysum + xcv * dpv) * sz;
    }
}

// ---------------- host driver ----------------------------------------------
static inline dim3 gemm_grid(int M, int N) {
    return dim3((N + 127) / 128, (M + 127) / 128);
}

extern "C" void kernel_launch(void* const* d_in, const int* in_sizes, int n_in,
                              void* d_out, int out_size)
{
    const float* x       = (const float*)d_in[0];
    const float* u       = (const float*)d_in[1];
    const float* alpha   = (const float*)d_in[2];
    const float* W_delta = (const float*)d_in[3];
    const float* b_delta = (const float*)d_in[4];
    const float* W_proj  = (const float*)d_in[5];
    const float* b_proj  = (const float*)d_in[6];

    const float* W_in[2]   = {(const float*)d_in[7],  (const float*)d_in[16]};
    const float* conv_w[2] = {(const float*)d_in[8],  (const float*)d_in[17]};
    const float* conv_b[2] = {(const float*)d_in[9],  (const float*)d_in[18]};
    const float* W_x[2]    = {(const float*)d_in[10], (const float*)d_in[19]};
    const float* W_dt[2]   = {(const float*)d_in[11], (const float*)d_in[20]};
    const float* b_dt[2]   = {(const float*)d_in[12], (const float*)d_in[21]};
    const float* A_log[2]  = {(const float*)d_in[13], (const float*)d_in[22]};
    const float* Dp[2]     = {(const float*)d_in[14], (const float*)d_in[23]};
    const float* W_out[2]  = {(const float*)d_in[15], (const float*)d_in[24]};

    float* out = (float*)d_out;                    // (BT, DM)
    float* fwd_out = out + (size_t)BT * DM;        // (BT, DM)
    float* bwd_out = out + 2 * (size_t)BT * DM;    // (BT, DM)

    float *tmp, *xg, *xz, *xc, *xdb, *dt, *y;
    cudaGetSymbolAddress((void**)&tmp, g_tmp);
    cudaGetSymbolAddress((void**)&xg,  g_xg);
    cudaGetSymbolAddress((void**)&xz,  g_xz);
    cudaGetSymbolAddress((void**)&xc,  g_xc);
    cudaGetSymbolAddress((void**)&xdb, g_xdb);
    cudaGetSymbolAddress((void**)&dt,  g_dt);
    cudaGetSymbolAddress((void**)&y,   g_y);

    const size_t XZ_S  = (size_t)BT * 2 * DI;
    const size_t XC_S  = (size_t)BT * DI;
    const size_t XDB_S = (size_t)BT * XDBW;

    // 1) delta GEMM: tmp = x @ W_delta
    sgemm<<<gemm_grid(BT, DM), 256>>>(x, W_delta, tmp, nullptr,
                                      BT, DM, DM, DM, DM, DM, 0);
    // 2) gating elementwise
    gate_kernel<<<(BT * DM + 255) / 256, 256>>>(x, u, alpha, b_delta);

    for (int dir = 0; dir < 2; dir++) {
        // 3) xz = xg(logical order) @ W_in   (flip rows for bwd)
        sgemm<<<gemm_grid(BT, 2 * DI), 256>>>(
            xg, W_in[dir], xz + dir * XZ_S, nullptr,
            BT, 2 * DI, DM, DM, 2 * DI, 2 * DI, dir ? F_FLIPA : 0);
        // 4) depthwise conv + silu
        conv_kernel<<<(BT * DI + 255) / 256, 256>>>(conv_w[dir], conv_b[dir], dir);
        // 5) xdb = xc @ W_x
        sgemm<<<gemm_grid(BT, XDBW), 256>>>(
            xc + dir * XC_S, W_x[dir], xdb + dir * XDB_S, nullptr,
            BT, XDBW, DI, DI, XDBW, XDBW, 0);
        // 6) dt = softplus(dt_lo @ W_dt + b_dt)
        sgemm<<<gemm_grid(BT, DI), 256>>>(
            xdb + dir * XDB_S, W_dt[dir], dt + dir * XC_S, b_dt[dir],
            BT, DI, DTR, XDBW, DI, DI, F_BIAS | F_SP);
    }

    // 7) selective scan (both directions, fused skip + output gate)
    scan_kernel<<<dim3(DI / 256, BSZ, 2), 256>>>(A_log[0], Dp[0], A_log[1], Dp[1]);

    // 8) out_dir = y @ W_out  (bwd: flip rows on store -> physical time order)
    sgemm<<<gemm_grid(BT, DM), 256>>>(y, W_out[0], fwd_out, nullptr,
                                      BT, DM, DI, DI, DM, DM, 0);
    sgemm<<<gemm_grid(BT, DM), 256>>>(y + XC_S, W_out[1], bwd_out, nullptr,
                                      BT, DM, DI, DI, DM, DM, F_FLIPC);

    // 9) out = fwd_out @ W_proj[:D] + bwd_out @ W_proj[D:] + b_proj
    sgemm<<<gemm_grid(BT, DM), 256>>>(fwd_out, W_proj, out, b_proj,
                                      BT, DM, DM, DM, DM, DM, F_BIAS);
    sgemm<<<gemm_grid(BT, DM), 256>>>(bwd_out, W_proj + (size_t)DM * DM, out, nullptr,
                                      BT, DM, DM, DM, DM, DM, F_ACC);
}

// round 5
// speedup vs baseline: 1.4867x; 1.4867x over previous
#include <cuda_runtime.h>
#include <cuda_bf16.h>
#include <math.h>
#include <stdint.h>

#define BSZ   2
#define TLEN  2048
#define DM    1024
#define DI    2048
#define DS    16
#define DTR   64
#define BT    4096     // BSZ*TLEN
#define XDBW  96       // DTR + 2*DS

// epilogue flags
#define F_FLIPA 1
#define F_FLIPC 2
#define F_ACC   4
#define F_BIAS  8
#define F_SP    16
#define F_PAIR  32

// ==================== scratch (device globals) =============================
__device__ float g_tmp[BT * DM];                 // x @ W_delta
__device__ float g_xz [2][BT * (2 * DI)];        // per-dir [xi | z]
__device__ float g_xc [2][BT * DI];              // conv+silu output (fp32, for scan)
__device__ float g_xdb[2][BT * XDBW];            // [dt_lo | B | C]
__device__ float g_dt [2][BT * DI];              // softplus(dt)

// bf16 split pairs (activations)
__device__ __nv_bfloat16 g_xh [BT * DM],  g_xl [BT * DM];
__device__ __nv_bfloat16 g_xgh[BT * DM],  g_xgl[BT * DM];
__device__ __nv_bfloat16 g_xch[2][BT * DI], g_xcl[2][BT * DI];
__device__ __nv_bfloat16 g_dlh[2][BT * DTR], g_dll[2][BT * DTR];
__device__ __nv_bfloat16 g_yh [2][BT * DI], g_yl [2][BT * DI];
__device__ __nv_bfloat16 g_oph[2][BT * DM], g_opl[2][BT * DM];

// bf16 split pairs (transposed weights, [N,K] K-major)
__device__ __nv_bfloat16 g_WdTh[DM * DM],        g_WdTl[DM * DM];
__device__ __nv_bfloat16 g_WinTh[2][4 * DM * DM], g_WinTl[2][4 * DM * DM];
__device__ __nv_bfloat16 g_WxTh[2][128 * DI],    g_WxTl[2][128 * DI];   // padded N=128
__device__ __nv_bfloat16 g_WdtTh[2][DI * DTR],   g_WdtTl[2][DI * DTR];
__device__ __nv_bfloat16 g_WoTh[2][DM * DI],     g_WoTl[2][DM * DI];
__device__ __nv_bfloat16 g_WpTh[2][DM * DM],     g_WpTl[2][DM * DM];

// ==================== helpers ==============================================
__device__ __forceinline__ uint32_t smem_u32(const void* p) {
    uint32_t a;
    asm("{ .reg .u64 t; cvta.to.shared.u64 t, %1; cvt.u32.u64 %0, t; }"
        : "=r"(a) : "l"(p));
    return a;
}
__device__ __forceinline__ float softplusf(float v) {
    return v > 20.f ? v : log1pf(expf(v));
}
__device__ __forceinline__ void split_bf16(float v, __nv_bfloat16& h, __nv_bfloat16& l) {
    h = __float2bfloat16(v);
    l = __float2bfloat16(v - __bfloat162float(h));
}

__device__ __forceinline__ void cp16(uint32_t s, const void* g) {
    asm volatile("cp.async.cg.shared.global [%0], [%1], 16;" :: "r"(s), "l"(g) : "memory");
}
__device__ __forceinline__ void cp_commit() {
    asm volatile("cp.async.commit_group;" ::: "memory");
}
template <int N> __device__ __forceinline__ void cp_wait() {
    asm volatile("cp.async.wait_group %0;" :: "n"(N) : "memory");
}
__device__ __forceinline__ void ldm_x4(uint32_t* r, uint32_t addr) {
    asm volatile("ldmatrix.sync.aligned.m8n8.x4.shared.b16 {%0,%1,%2,%3}, [%4];"
                 : "=r"(r[0]), "=r"(r[1]), "=r"(r[2]), "=r"(r[3]) : "r"(addr));
}
__device__ __forceinline__ void mma16816(float* c, const uint32_t* a, uint32_t b0, uint32_t b1) {
    asm volatile(
        "mma.sync.aligned.m16n8k16.row.col.f32.bf16.bf16.f32 "
        "{%0,%1,%2,%3}, {%4,%5,%6,%7}, {%8,%9}, {%0,%1,%2,%3};"
        : "+f"(c[0]), "+f"(c[1]), "+f"(c[2]), "+f"(c[3])
        : "r"(a[0]), "r"(a[1]), "r"(a[2]), "r"(a[3]), "r"(b0), "r"(b1));
}

// ==================== HMMA GEMM ============================================
// C[M,N] = (Ah+Al)[M,K] @ (Bh+Bl)[N,K]^T   (3 split terms: hh + hl + lh)
// 128x128 tile, BK=32, 8 warps x (32m x 64n), cp.async double buffer.
#define KSTRIDE  80                       // padded row stride (bytes) for 32 bf16
#define TILE_B   (128 * KSTRIDE)          // 10240
#define STAGE_B  (4 * TILE_B)             // 40960
#define GEMM_SMEM (2 * STAGE_B)           // 81920

__global__ __launch_bounds__(256)
void tcgemm(const __nv_bfloat16* __restrict__ Ah, const __nv_bfloat16* __restrict__ Al,
            const __nv_bfloat16* __restrict__ Bh, const __nv_bfloat16* __restrict__ Bl,
            float* __restrict__ C, const float* __restrict__ bias,
            __nv_bfloat16* __restrict__ Ph, __nv_bfloat16* __restrict__ Pl,
            int M, int N, int K, int ldc, int pairN, int flags)
{
    extern __shared__ __align__(128) char smem[];
    const uint32_t sbase = smem_u32(smem);
    const int tid  = threadIdx.x;
    const int lane = tid & 31;
    const int wid  = tid >> 5;
    const int warp_m = wid >> 1;      // 0..3
    const int warp_n = wid & 1;       // 0..1
    const int bm = blockIdx.y * 128;
    const int bn = blockIdx.x * 128;

    // ---- load geometry (per-thread, constant across chunks) ----
    size_t   a_goff[2], b_goff[2];
    uint32_t s_off[2];
#pragma unroll
    for (int i = 0; i < 2; i++) {
        int row = (tid + i * 256) >> 2;         // 0..127
        int seg = tid & 3;                      // 16B segment
        int am = bm + row;
        if (flags & F_FLIPA) { int b_ = am / TLEN, t_ = am % TLEN; am = b_ * TLEN + (TLEN - 1 - t_); }
        a_goff[i] = ((size_t)am * K + seg * 8) * 2;
        b_goff[i] = ((size_t)(bn + row) * K + seg * 8) * 2;
        s_off[i]  = row * KSTRIDE + seg * 16;
    }

    // ---- ldmatrix lane addressing ----
    const int a_lm_row = lane & 15;
    const int a_lm_cb  = (lane >> 4) * 16;
    const int b_lm_row = (lane & 7) + ((lane >> 4) & 1) * 8;
    const int b_lm_cb  = ((lane >> 3) & 1) * 16;
    const uint32_t a_pre = (warp_m * 32 + a_lm_row) * KSTRIDE + a_lm_cb;
    const uint32_t b_pre = (warp_n * 64 + b_lm_row) * KSTRIDE + b_lm_cb;

    float acc[2][8][4];
#pragma unroll
    for (int mt = 0; mt < 2; mt++)
#pragma unroll
        for (int nt = 0; nt < 8; nt++)
#pragma unroll
            for (int q = 0; q < 4; q++) acc[mt][nt][q] = 0.f;

    const int NC = K / 32;

    // ---- prologue: issue chunks 0,1 ----
#pragma unroll
    for (int c = 0; c < 2; c++) {
        if (c < NC) {
            uint32_t sb = sbase + (c & 1) * STAGE_B;
            size_t cb = (size_t)c * 64;
#pragma unroll
            for (int i = 0; i < 2; i++) {
                cp16(sb +            s_off[i], (const char*)Ah + a_goff[i] + cb);
                cp16(sb + TILE_B   + s_off[i], (const char*)Al + a_goff[i] + cb);
                cp16(sb + 2*TILE_B + s_off[i], (const char*)Bh + b_goff[i] + cb);
                cp16(sb + 3*TILE_B + s_off[i], (const char*)Bl + b_goff[i] + cb);
            }
            cp_commit();
        }
    }

    for (int c = 0; c < NC; c++) {
        if (c + 2 <= NC) cp_wait<1>(); else cp_wait<0>();
        __syncthreads();

        const uint32_t st = sbase + (c & 1) * STAGE_B;
#pragma unroll
        for (int kk = 0; kk < 2; kk++) {
            const uint32_t kb = kk * 32;
            uint32_t a_h[2][4], a_l[2][4];
#pragma unroll
            for (int mt = 0; mt < 2; mt++) {
                ldm_x4(a_h[mt], st +          a_pre + mt * 16 * KSTRIDE + kb);
                ldm_x4(a_l[mt], st + TILE_B + a_pre + mt * 16 * KSTRIDE + kb);
            }
            uint32_t b_h[8][2], b_l[8][2];
#pragma unroll
            for (int p = 0; p < 4; p++) {
                uint32_t r[4];
                ldm_x4(r, st + 2*TILE_B + b_pre + p * 16 * KSTRIDE + kb);
                b_h[2*p][0] = r[0]; b_h[2*p][1] = r[1];
                b_h[2*p+1][0] = r[2]; b_h[2*p+1][1] = r[3];
                ldm_x4(r, st + 3*TILE_B + b_pre + p * 16 * KSTRIDE + kb);
                b_l[2*p][0] = r[0]; b_l[2*p][1] = r[1];
                b_l[2*p+1][0] = r[2]; b_l[2*p+1][1] = r[3];
            }
#pragma unroll
            for (int mt = 0; mt < 2; mt++)
#pragma unroll
                for (int nt = 0; nt < 8; nt++) {
                    mma16816(acc[mt][nt], a_h[mt], b_h[nt][0], b_h[nt][1]);
                    mma16816(acc[mt][nt], a_h[mt], b_l[nt][0], b_l[nt][1]);
                    mma16816(acc[mt][nt], a_l[mt], b_h[nt][0], b_h[nt][1]);
                }
        }
        __syncthreads();

        if (c + 2 < NC) {
            uint32_t sb = sbase + ((c + 2) & 1) * STAGE_B;
            size_t cb = (size_t)(c + 2) * 64;
#pragma unroll
            for (int i = 0; i < 2; i++) {
                cp16(sb +            s_off[i], (const char*)Ah + a_goff[i] + cb);
                cp16(sb + TILE_B   + s_off[i], (const char*)Al + a_goff[i] + cb);
                cp16(sb + 2*TILE_B + s_off[i], (const char*)Bh + b_goff[i] + cb);
                cp16(sb + 3*TILE_B + s_off[i], (const char*)Bl + b_goff[i] + cb);
            }
            cp_commit();
        }
    }

    // ---- epilogue ----
    const int row_in = lane >> 2;
    const int col_in = (lane & 3) * 2;
#pragma unroll
    for (int mt = 0; mt < 2; mt++) {
#pragma unroll
        for (int half = 0; half < 2; half++) {
            int gm = bm + warp_m * 32 + mt * 16 + row_in + half * 8;
            int gmp = gm;
            if (flags & F_FLIPC) { int b_ = gm / TLEN, t_ = gm % TLEN; gmp = b_ * TLEN + (TLEN - 1 - t_); }
#pragma unroll
            for (int nt = 0; nt < 8; nt++) {
                int gn = bn + warp_n * 64 + nt * 8 + col_in;
                if (gn >= N) continue;
                float v0 = acc[mt][nt][half * 2 + 0];
                float v1 = acc[mt][nt][half * 2 + 1];
                size_t ci = (size_t)gmp * ldc + gn;
                if (flags & F_ACC)  { v0 += C[ci]; v1 += C[ci + 1]; }
                if (flags & F_BIAS) { v0 += bias[gn]; v1 += bias[gn + 1]; }
                if (flags & F_SP)   { v0 = softplusf(v0); v1 = softplusf(v1); }
                C[ci]     = v0;
                C[ci + 1] = v1;
                if ((flags & F_PAIR) && gn < pairN) {
                    size_t pi = (size_t)gmp * pairN + gn;
                    __nv_bfloat16 h, l;
                    split_bf16(v0, h, l); Ph[pi] = h;     Pl[pi] = l;
                    split_bf16(v1, h, l); Ph[pi + 1] = h; Pl[pi + 1] = l;
                }
            }
        }
    }
}

// ==================== transpose + bf16-split weights =======================
__global__ void wtrans_kernel(const float* __restrict__ W,
                              __nv_bfloat16* __restrict__ Th,
                              __nv_bfloat16* __restrict__ Tl,
                              int K, int N)
{
    __shared__ float tile[32][33];
    int k0 = blockIdx.x * 32, n0 = blockIdx.y * 32;
    int tx = threadIdx.x, ty = threadIdx.y;   // 32 x 8
#pragma unroll
    for (int i = 0; i < 32; i += 8) {
        int k = k0 + ty + i, n = n0 + tx;
        tile[ty + i][tx] = (n < N) ? W[(size_t)k * N + n] : 0.f;
    }
    __syncthreads();
#pragma unroll
    for (int i = 0; i < 32; i += 8) {
        int n = n0 + ty + i, k = k0 + tx;
        float v = tile[tx][ty + i];
        __nv_bfloat16 h, l;
        split_bf16(v, h, l);
        Th[(size_t)n * K + k] = h;
        Tl[(size_t)n * K + k] = l;
    }
}

// ==================== fp32 -> bf16 pair ====================================
__global__ void pairify_kernel(const float* __restrict__ src,
                               __nv_bfloat16* __restrict__ h,
                               __nv_bfloat16* __restrict__ l, int n)
{
    int idx = blockIdx.x * blockDim.x + threadIdx.x;
    if (idx >= n) return;
    __nv_bfloat16 hh, ll;
    split_bf16(src[idx], hh, ll);
    h[idx] = hh; l[idx] = ll;
}

// ==================== quality gating =======================================
__global__ void gate_kernel(const float* __restrict__ x,
                            const float* __restrict__ u,
                            const float* __restrict__ alpha,
                            const float* __restrict__ b_delta)
{
    int idx = blockIdx.x * blockDim.x + threadIdx.x;
    if (idx >= BT * DM) return;
    int r = idx / DM, c = idx % DM;
    float v        = g_tmp[idx] + b_delta[c];
    float draw     = softplusf(v);
    float delta_id = draw * expf(-alpha[0] * u[r]);
    float gate     = delta_id / (1.f + delta_id);
    float xgv = x[idx] * gate;
    __nv_bfloat16 h, l;
    split_bf16(xgv, h, l);
    g_xgh[idx] = h; g_xgl[idx] = l;
}

// ==================== causal depthwise conv + silu =========================
__global__ void conv_kernel(const float* __restrict__ cw,
                            const float* __restrict__ cb, int dir)
{
    int idx = blockIdx.x * blockDim.x + threadIdx.x;
    if (idx >= BT * DI) return;
    int r = idx / DI, c = idx % DI;
    int t = r % TLEN;
    const float* xzp = g_xz[dir];
    float acc = cb[c];
#pragma unroll
    for (int k = 0; k < 4; k++) {
        int ts = t - 3 + k;
        if (ts >= 0)
            acc = fmaf(cw[c * 4 + k], xzp[(size_t)(r - 3 + k) * (2 * DI) + c], acc);
    }
    float v = acc / (1.f + __expf(-acc));
    g_xc[dir][idx] = v;
    __nv_bfloat16 h, l;
    split_bf16(v, h, l);
    g_xch[dir][idx] = h; g_xcl[dir][idx] = l;
}

// ==================== selective scan =======================================
__global__ void scan_kernel(const float* __restrict__ Af,
                            const float* __restrict__ Dpf,
                            const float* __restrict__ Ab,
                            const float* __restrict__ Dpb)
{
    const int dir = blockIdx.z;
    const int b   = blockIdx.y;
    const int d   = blockIdx.x * blockDim.x + threadIdx.x;

    const float* Alog = dir ? Ab  : Af;
    const float* Dp   = dir ? Dpb : Dpf;

    float a[DS], h[DS];
#pragma unroll
    for (int s = 0; s < DS; s++) {
        a[s] = -expf(Alog[d * DS + s]);
        h[s] = 0.f;
    }
    const float dpv = Dp[d];

    const float* dtp  = g_dt[dir];
    const float* xcp  = g_xc[dir];
    const float* xzp  = g_xz[dir];
    const float* xdbp = g_xdb[dir];
    __nv_bfloat16* yh = g_yh[dir];
    __nv_bfloat16* yl = g_yl[dir];

    for (int t = 0; t < TLEN; t++) {
        int    r    = b * TLEN + t;
        size_t base = (size_t)r * DI + d;
        float dtv = dtp[base];
        float xcv = xcp[base];
        float zv  = xzp[(size_t)r * (2 * DI) + DI + d];

        float Bv[DS], Cv[DS];
        const float4* bp4 = (const float4*)(xdbp + (size_t)r * XDBW + DTR);
        const float4* cp4 = (const float4*)(xdbp + (size_t)r * XDBW + DTR + DS);
#pragma unroll
        for (int q = 0; q < 4; q++) {
            float4 bb = __ldg(bp4 + q);
            float4 cc = __ldg(cp4 + q);
            Bv[q*4+0]=bb.x; Bv[q*4+1]=bb.y; Bv[q*4+2]=bb.z; Bv[q*4+3]=bb.w;
            Cv[q*4+0]=cc.x; Cv[q*4+1]=cc.y; Cv[q*4+2]=cc.z; Cv[q*4+3]=cc.w;
        }

        float dtx  = dtv * xcv;
        float ysum = 0.f;
#pragma unroll
        for (int s = 0; s < DS; s++) {
            float dA = __expf(dtv * a[s]);
            h[s] = fmaf(dA, h[s], dtx * Bv[s]);
            ysum = fmaf(h[s], Cv[s], ysum);
        }
        float sz = zv / (1.f + __expf(-zv));
        float yv = (ysum + xcv * dpv) * sz;
        __nv_bfloat16 hh, ll;
        split_bf16(yv, hh, ll);
        yh[base] = hh; yl[base] = ll;
    }
}

// ==================== host driver ==========================================
typedef __nv_bfloat16 bf16;

static inline dim3 ggrid(int M, int N) { return dim3((N + 127) / 128, M / 128); }

extern "C" void kernel_launch(void* const* d_in, const int* in_sizes, int n_in,
                              void* d_out, int out_size)
{
    const float* x       = (const float*)d_in[0];
    const float* u       = (const float*)d_in[1];
    const float* alpha   = (const float*)d_in[2];
    const float* W_delta = (const float*)d_in[3];
    const float* b_delta = (const float*)d_in[4];
    const float* W_proj  = (const float*)d_in[5];
    const float* b_proj  = (const float*)d_in[6];

    const float* W_in[2]   = {(const float*)d_in[7],  (const float*)d_in[16]};
    const float* conv_w[2] = {(const float*)d_in[8],  (const float*)d_in[17]};
    const float* conv_b[2] = {(const float*)d_in[9],  (const float*)d_in[18]};
    const float* W_x[2]    = {(const float*)d_in[10], (const float*)d_in[19]};
    const float* W_dt[2]   = {(const float*)d_in[11], (const float*)d_in[20]};
    const float* b_dt[2]   = {(const float*)d_in[12], (const float*)d_in[21]};
    const float* A_log[2]  = {(const float*)d_in[13], (const float*)d_in[22]};
    const float* Dp[2]     = {(const float*)d_in[14], (const float*)d_in[23]};
    const float* W_out[2]  = {(const float*)d_in[15], (const float*)d_in[24]};

    float* out     = (float*)d_out;
    float* fwd_out = out + (size_t)BT * DM;
    float* bwd_out = out + 2 * (size_t)BT * DM;

    float *tmp, *xz, *xc, *xdb, *dt;
    cudaGetSymbolAddress((void**)&tmp, g_tmp);
    cudaGetSymbolAddress((void**)&xz,  g_xz);
    cudaGetSymbolAddress((void**)&xc,  g_xc);
    cudaGetSymbolAddress((void**)&xdb, g_xdb);
    cudaGetSymbolAddress((void**)&dt,  g_dt);

    bf16 *xh, *xl, *xgh, *xgl, *xch, *xcl, *dlh, *dll, *yh, *yl, *oph, *opl;
    cudaGetSymbolAddress((void**)&xh,  g_xh);   cudaGetSymbolAddress((void**)&xl,  g_xl);
    cudaGetSymbolAddress((void**)&xgh, g_xgh);  cudaGetSymbolAddress((void**)&xgl, g_xgl);
    cudaGetSymbolAddress((void**)&xch, g_xch);  cudaGetSymbolAddress((void**)&xcl, g_xcl);
    cudaGetSymbolAddress((void**)&dlh, g_dlh);  cudaGetSymbolAddress((void**)&dll, g_dll);
    cudaGetSymbolAddress((void**)&yh,  g_yh);   cudaGetSymbolAddress((void**)&yl,  g_yl);
    cudaGetSymbolAddress((void**)&oph, g_oph);  cudaGetSymbolAddress((void**)&opl, g_opl);

    bf16 *WdTh, *WdTl, *WinTh, *WinTl, *WxTh, *WxTl, *WdtTh, *WdtTl, *WoTh, *WoTl, *WpTh, *WpTl;
    cudaGetSymbolAddress((void**)&WdTh,  g_WdTh);  cudaGetSymbolAddress((void**)&WdTl,  g_WdTl);
    cudaGetSymbolAddress((void**)&WinTh, g_WinTh); cudaGetSymbolAddress((void**)&WinTl, g_WinTl);
    cudaGetSymbolAddress((void**)&WxTh,  g_WxTh);  cudaGetSymbolAddress((void**)&WxTl,  g_WxTl);
    cudaGetSymbolAddress((void**)&WdtTh, g_WdtTh); cudaGetSymbolAddress((void**)&WdtTl, g_WdtTl);
    cudaGetSymbolAddress((void**)&WoTh,  g_WoTh);  cudaGetSymbolAddress((void**)&WoTl,  g_WoTl);
    cudaGetSymbolAddress((void**)&WpTh,  g_WpTh);  cudaGetSymbolAddress((void**)&WpTl,  g_WpTl);

    cudaFuncSetAttribute(tcgemm, cudaFuncAttributeMaxDynamicSharedMemorySize, GEMM_SMEM);

    const size_t XZ_S  = (size_t)BT * 2 * DI;
    const size_t XC_S  = (size_t)BT * DI;
    const size_t XDB_S = (size_t)BT * XDBW;
    const size_t DL_S  = (size_t)BT * DTR;
    const size_t OP_S  = (size_t)BT * DM;
    const size_t WIN_S = (size_t)4 * DM * DM;
    const size_t WX_S  = (size_t)128 * DI;
    const size_t WDT_S = (size_t)DI * DTR;
    const size_t WO_S  = (size_t)DM * DI;
    const size_t WP_S  = (size_t)DM * DM;

    dim3 tb(32, 8);
    wtrans_kernel<<<dim3(DM / 32, DM / 32), tb>>>(W_delta, WdTh, WdTl, DM, DM);
    for (int d2 = 0; d2 < 2; d2++) {
        wtrans_kernel<<<dim3(DM / 32, (4 * DM) / 32), tb>>>(W_in[d2],  WinTh + d2 * WIN_S, WinTl + d2 * WIN_S, DM, 4 * DM);
        wtrans_kernel<<<dim3(DI / 32, 128 / 32), tb>>>(W_x[d2],   WxTh  + d2 * WX_S,  WxTl  + d2 * WX_S,  DI, XDBW);
        wtrans_kernel<<<dim3(DTR / 32, DI / 32), tb>>>(W_dt[d2],  WdtTh + d2 * WDT_S, WdtTl + d2 * WDT_S, DTR, DI);
        wtrans_kernel<<<dim3(DI / 32, DM / 32), tb>>>(W_out[d2],  WoTh  + d2 * WO_S,  WoTl  + d2 * WO_S,  DI, DM);
        wtrans_kernel<<<dim3(DM / 32, DM / 32), tb>>>(W_proj + (size_t)d2 * DM * DM,
                                                      WpTh + d2 * WP_S, WpTl + d2 * WP_S, DM, DM);
    }
    pairify_kernel<<<(BT * DM + 255) / 256, 256>>>(x, xh, xl, BT * DM);

    // 1) tmp = x @ W_delta
    tcgemm<<<ggrid(BT, DM), 256, GEMM_SMEM>>>(xh, xl, WdTh, WdTl, tmp, nullptr,
                                              nullptr, nullptr, BT, DM, DM, DM, 0, 0);
    // 2) gate -> xg pair
    gate_kernel<<<(BT * DM + 255) / 256, 256>>>(x, u, alpha, b_delta);

    for (int d2 = 0; d2 < 2; d2++) {
        // 3) xz = xg @ W_in  (bwd: flip A rows within T)
        tcgemm<<<ggrid(BT, 4 * DM), 256, GEMM_SMEM>>>(
            xgh, xgl, WinTh + d2 * WIN_S, WinTl + d2 * WIN_S,
            xz + d2 * XZ_S, nullptr, nullptr, nullptr,
            BT, 4 * DM, DM, 4 * DM, 0, d2 ? F_FLIPA : 0);
        // 4) conv + silu -> xc fp32 + pair
        conv_kernel<<<(BT * DI + 255) / 256, 256>>>(conv_w[d2], conv_b[d2], d2);
        // 5) xdb = xc @ W_x  (+pair of first 64 cols -> dt_lo pair)
        tcgemm<<<ggrid(BT, XDBW), 256, GEMM_SMEM>>>(
            xch + d2 * XC_S, xcl + d2 * XC_S, WxTh + d2 * WX_S, WxTl + d2 * WX_S,
            xdb + d2 * XDB_S, nullptr, dlh + d2 * DL_S, dll + d2 * DL_S,
            BT, XDBW, DI, XDBW, DTR, F_PAIR);
        // 6) dt = softplus(dt_lo @ W_dt + b_dt)
        tcgemm<<<ggrid(BT, DI), 256, GEMM_SMEM>>>(
            dlh + d2 * DL_S, dll + d2 * DL_S, WdtTh + d2 * WDT_S, WdtTl + d2 * WDT_S,
            dt + d2 * XC_S, b_dt[d2], nullptr, nullptr,
            BT, DI, DTR, DI, 0, F_BIAS | F_SP);
    }

    // 7) selective scan -> y pair
    scan_kernel<<<dim3(DI / 256, BSZ, 2), 256>>>(A_log[0], Dp[0], A_log[1], Dp[1]);

    // 8) out_dir = y @ W_out  (bwd flips C rows)
    tcgemm<<<ggrid(BT, DM), 256, GEMM_SMEM>>>(
        yh, yl, WoTh, WoTl, fwd_out, nullptr, oph, opl,
        BT, DM, DI, DM, DM, F_PAIR);
    tcgemm<<<ggrid(BT, DM), 256, GEMM_SMEM>>>(
        yh + XC_S, yl + XC_S, WoTh + WO_S, WoTl + WO_S, bwd_out, nullptr,
        oph + OP_S, opl + OP_S,
        BT, DM, DI, DM, DM, F_PAIR | F_FLIPC);

    // 9) out = fwd_out @ Wp1 + bwd_out @ Wp2 + b_proj
    tcgemm<<<ggrid(BT, DM), 256, GEMM_SMEM>>>(
        oph, opl, WpTh, WpTl, out, b_proj, nullptr, nullptr,
        BT, DM, DM, DM, 0, F_BIAS);
    tcgemm<<<ggrid(BT, DM), 256, GEMM_SMEM>>>(
        oph + OP_S, opl + OP_S, WpTh + WP_S, WpTl + WP_S, out, nullptr, nullptr, nullptr,
        BT, DM, DM, DM, 0, F_ACC);
}

// round 7
// speedup vs baseline: 2.1103x; 1.4195x over previous
#include <cuda_runtime.h>
#include <cuda_bf16.h>
#include <math.h>
#include <stdint.h>

#define BSZ   2
#define TLEN  2048
#define DM    1024
#define DI    2048
#define DS    16
#define DTR   64
#define BT    4096     // BSZ*TLEN
#define XDBW  96       // DTR + 2*DS

// epilogue flags
#define F_FLIPA 1
#define F_FLIPC 2
#define F_ACC   4
#define F_BIAS  8
#define F_SP    16
#define F_PAIR  32

typedef __nv_bfloat16 bf16;

// ==================== scratch (device globals) =============================
__device__ float g_tmp[BT * DM];                 // x @ W_delta
__device__ float g_xz [2][BT * (2 * DI)];        // per-dir [xi | z]
__device__ float g_xc [2][BT * DI];              // conv+silu output (fp32, for scan)
__device__ float g_xdb[2][BT * XDBW];            // [dt_lo | B | C]
__device__ float g_dt [2][BT * DI];              // softplus(dt)

// bf16 split pairs (activations)
__device__ bf16 g_xh [BT * DM],  g_xl [BT * DM];
__device__ bf16 g_xgh[BT * DM],  g_xgl[BT * DM];
__device__ bf16 g_xch[2][BT * DI], g_xcl[2][BT * DI];
__device__ bf16 g_dlh[2][BT * DTR], g_dll[2][BT * DTR];
__device__ bf16 g_yh [2][BT * DI], g_yl [2][BT * DI];
__device__ bf16 g_opch[BT * 2 * DM], g_opcl[BT * 2 * DM];  // concat fwd|bwd

// bf16 split pairs (transposed weights, [N,K] K-major)
__device__ bf16 g_WdTh[DM * DM],        g_WdTl[DM * DM];
__device__ bf16 g_WinTh[2][4 * DM * DM], g_WinTl[2][4 * DM * DM];
__device__ bf16 g_WxTh[2][128 * DI],    g_WxTl[2][128 * DI];   // padded N=128
__device__ bf16 g_WdtTh[2][DI * DTR],   g_WdtTl[2][DI * DTR];
__device__ bf16 g_WoTh[2][DM * DI],     g_WoTl[2][DM * DI];
__device__ bf16 g_WpTh[DM * 2 * DM],    g_WpTl[DM * 2 * DM];   // [1024, 2048]

// ==================== helpers ==============================================
__device__ __forceinline__ uint32_t smem_u32(const void* p) {
    uint32_t a;
    asm("{ .reg .u64 t; cvta.to.shared.u64 t, %1; cvt.u32.u64 %0, t; }"
        : "=r"(a) : "l"(p));
    return a;
}
__device__ __forceinline__ float softplusf(float v) {
    return v > 20.f ? v : log1pf(expf(v));
}
__device__ __forceinline__ void split_bf16(float v, bf16& h, bf16& l) {
    h = __float2bfloat16(v);
    l = __float2bfloat16(v - __bfloat162float(h));
}
__device__ __forceinline__ void cp16(uint32_t s, const void* g) {
    asm volatile("cp.async.cg.shared.global [%0], [%1], 16;" :: "r"(s), "l"(g) : "memory");
}
__device__ __forceinline__ void cp_commit() {
    asm volatile("cp.async.commit_group;" ::: "memory");
}
template <int N> __device__ __forceinline__ void cp_wait() {
    asm volatile("cp.async.wait_group %0;" :: "n"(N) : "memory");
}
__device__ __forceinline__ void ldm_x4(uint32_t* r, uint32_t addr) {
    asm volatile("ldmatrix.sync.aligned.m8n8.x4.shared.b16 {%0,%1,%2,%3}, [%4];"
                 : "=r"(r[0]), "=r"(r[1]), "=r"(r[2]), "=r"(r[3]) : "r"(addr));
}
__device__ __forceinline__ void mma16816(float* c, const uint32_t* a, uint32_t b0, uint32_t b1) {
    asm volatile(
        "mma.sync.aligned.m16n8k16.row.col.f32.bf16.bf16.f32 "
        "{%0,%1,%2,%3}, {%4,%5,%6,%7}, {%8,%9}, {%0,%1,%2,%3};"
        : "+f"(c[0]), "+f"(c[1]), "+f"(c[2]), "+f"(c[3])
        : "r"(a[0]), "r"(a[1]), "r"(a[2]), "r"(a[3]), "r"(b0), "r"(b1));
}

// ==================== HMMA GEMM ============================================
// C[M,N] = (Ah+Al)[M,K] @ (Bh+Bl)[N,K]^T   (3 split terms: hh + hl + lh)
// 128x128 tile, BK=32, 8 warps x (32m x 64n), 3-stage cp.async pipeline.
// blockIdx.z selects direction; per-z pointer strides + flags.
#define KSTRIDE  80
#define TILE_B   (128 * KSTRIDE)          // 10240
#define STAGE_B  (4 * TILE_B)             // 40960
#define GEMM_SMEM (3 * STAGE_B)           // 122880

__global__ __launch_bounds__(256)
void tcgemm(const bf16* __restrict__ Ah, const bf16* __restrict__ Al,
            const bf16* __restrict__ Bh, const bf16* __restrict__ Bl,
            float* __restrict__ C, const float* __restrict__ bias0,
            const float* __restrict__ bias1,
            bf16* __restrict__ Ph, bf16* __restrict__ Pl,
            int M, int N, int K, int ldc, int pairN, int pairLd,
            long long sA, long long sB, long long sC, long long sP,
            int flags0, int flags1)
{
    extern __shared__ __align__(128) char smem[];
    const uint32_t sbase = smem_u32(smem);
    const int z = blockIdx.z;
    const int flags = z ? flags1 : flags0;
    const float* bias = z ? bias1 : bias0;
    Ah += z * sA; Al += z * sA;
    Bh += z * sB; Bl += z * sB;
    C  += z * sC;
    const long long poff = (long long)z * sP;

    const int tid  = threadIdx.x;
    const int lane = tid & 31;
    const int wid  = tid >> 5;
    const int warp_m = wid >> 1;      // 0..3
    const int warp_n = wid & 1;       // 0..1
    const int bm = blockIdx.y * 128;
    const int bn = blockIdx.x * 128;

    // ---- load geometry ----
    size_t   a_goff[2], b_goff[2];
    uint32_t s_off[2];
#pragma unroll
    for (int i = 0; i < 2; i++) {
        int row = (tid + i * 256) >> 2;
        int seg = tid & 3;
        int am = bm + row;
        if (flags & F_FLIPA) { int b_ = am / TLEN, t_ = am % TLEN; am = b_ * TLEN + (TLEN - 1 - t_); }
        a_goff[i] = ((size_t)am * K + seg * 8) * 2;
        b_goff[i] = ((size_t)(bn + row) * K + seg * 8) * 2;
        s_off[i]  = row * KSTRIDE + seg * 16;
    }

    const int a_lm_row = lane & 15;
    const int a_lm_cb  = (lane >> 4) * 16;
    const int b_lm_row = (lane & 7) + ((lane >> 4) & 1) * 8;
    const int b_lm_cb  = ((lane >> 3) & 1) * 16;
    const uint32_t a_pre = (warp_m * 32 + a_lm_row) * KSTRIDE + a_lm_cb;
    const uint32_t b_pre = (warp_n * 64 + b_lm_row) * KSTRIDE + b_lm_cb;

    float acc[2][8][4];
#pragma unroll
    for (int mt = 0; mt < 2; mt++)
#pragma unroll
        for (int nt = 0; nt < 8; nt++)
#pragma unroll
            for (int q = 0; q < 4; q++) acc[mt][nt][q] = 0.f;

    const int NC = K / 32;
    const int pre = NC < 3 ? NC : 3;

    // issue helper inlined
#define ISSUE(cc) do {                                                        \
        uint32_t sb = sbase + ((cc) % 3) * STAGE_B;                           \
        size_t cbv = (size_t)(cc) * 64;                                       \
        _Pragma("unroll")                                                     \
        for (int i = 0; i < 2; i++) {                                         \
            cp16(sb +            s_off[i], (const char*)Ah + a_goff[i] + cbv);\
            cp16(sb + TILE_B   + s_off[i], (const char*)Al + a_goff[i] + cbv);\
            cp16(sb + 2*TILE_B + s_off[i], (const char*)Bh + b_goff[i] + cbv);\
            cp16(sb + 3*TILE_B + s_off[i], (const char*)Bl + b_goff[i] + cbv);\
        }                                                                     \
        cp_commit();                                                          \
    } while (0)

    for (int c = 0; c < pre; c++) ISSUE(c);
    int issued = pre;

    for (int c = 0; c < NC; c++) {
        int rem = issued - c - 1;
        if (rem >= 2) cp_wait<2>();
        else if (rem == 1) cp_wait<1>();
        else cp_wait<0>();
        __syncthreads();

        const uint32_t st = sbase + (c % 3) * STAGE_B;
#pragma unroll
        for (int kk = 0; kk < 2; kk++) {
            const uint32_t kb = kk * 32;
            uint32_t a_h[2][4], a_l[2][4];
#pragma unroll
            for (int mt = 0; mt < 2; mt++) {
                ldm_x4(a_h[mt], st +          a_pre + mt * 16 * KSTRIDE + kb);
                ldm_x4(a_l[mt], st + TILE_B + a_pre + mt * 16 * KSTRIDE + kb);
            }
            uint32_t b_h[8][2], b_l[8][2];
#pragma unroll
            for (int p = 0; p < 4; p++) {
                uint32_t r[4];
                ldm_x4(r, st + 2*TILE_B + b_pre + p * 16 * KSTRIDE + kb);
                b_h[2*p][0] = r[0]; b_h[2*p][1] = r[1];
                b_h[2*p+1][0] = r[2]; b_h[2*p+1][1] = r[3];
                ldm_x4(r, st + 3*TILE_B + b_pre + p * 16 * KSTRIDE + kb);
                b_l[2*p][0] = r[0]; b_l[2*p][1] = r[1];
                b_l[2*p+1][0] = r[2]; b_l[2*p+1][1] = r[3];
            }
            // three passes: each accumulator touched once per pass -> no RAW chains
#pragma unroll
            for (int mt = 0; mt < 2; mt++)
#pragma unroll
                for (int nt = 0; nt < 8; nt++)
                    mma16816(acc[mt][nt], a_h[mt], b_h[nt][0], b_h[nt][1]);
#pragma unroll
            for (int mt = 0; mt < 2; mt++)
#pragma unroll
                for (int nt = 0; nt < 8; nt++)
                    mma16816(acc[mt][nt], a_h[mt], b_l[nt][0], b_l[nt][1]);
#pragma unroll
            for (int mt = 0; mt < 2; mt++)
#pragma unroll
                for (int nt = 0; nt < 8; nt++)
                    mma16816(acc[mt][nt], a_l[mt], b_h[nt][0], b_h[nt][1]);
        }
        __syncthreads();

        if (issued < NC) { ISSUE(issued); issued++; }
    }
#undef ISSUE

    // ---- epilogue ----
    const int row_in = lane >> 2;
    const int col_in = (lane & 3) * 2;
#pragma unroll
    for (int mt = 0; mt < 2; mt++) {
#pragma unroll
        for (int half = 0; half < 2; half++) {
            int gm = bm + warp_m * 32 + mt * 16 + row_in + half * 8;
            int gmp = gm;
            if (flags & F_FLIPC) { int b_ = gm / TLEN, t_ = gm % TLEN; gmp = b_ * TLEN + (TLEN - 1 - t_); }
#pragma unroll
            for (int nt = 0; nt < 8; nt++) {
                int gn = bn + warp_n * 64 + nt * 8 + col_in;
                if (gn >= N) continue;
                float v0 = acc[mt][nt][half * 2 + 0];
                float v1 = acc[mt][nt][half * 2 + 1];
                size_t ci = (size_t)gmp * ldc + gn;
                if (flags & F_ACC)  { v0 += C[ci]; v1 += C[ci + 1]; }
                if (flags & F_BIAS) { v0 += bias[gn]; v1 += bias[gn + 1]; }
                if (flags & F_SP)   { v0 = softplusf(v0); v1 = softplusf(v1); }
                C[ci]     = v0;
                C[ci + 1] = v1;
                if ((flags & F_PAIR) && gn < pairN) {
                    size_t pi = (size_t)(poff + (long long)gmp * pairLd + gn);
                    bf16 h, l;
                    split_bf16(v0, h, l); Ph[pi] = h;     Pl[pi] = l;
                    split_bf16(v1, h, l); Ph[pi + 1] = h; Pl[pi + 1] = l;
                }
            }
        }
    }
}

// ==================== transpose + bf16-split weights =======================
__global__ void wtrans_kernel(const float* __restrict__ W,
                              bf16* __restrict__ Th, bf16* __restrict__ Tl,
                              int K, int N)
{
    __shared__ float tile[32][33];
    int k0 = blockIdx.x * 32, n0 = blockIdx.y * 32;
    int tx = threadIdx.x, ty = threadIdx.y;   // 32 x 8
#pragma unroll
    for (int i = 0; i < 32; i += 8) {
        int k = k0 + ty + i, n = n0 + tx;
        tile[ty + i][tx] = (n < N) ? W[(size_t)k * N + n] : 0.f;
    }
    __syncthreads();
#pragma unroll
    for (int i = 0; i < 32; i += 8) {
        int n = n0 + ty + i, k = k0 + tx;
        float v = tile[tx][ty + i];
        bf16 h, l;
        split_bf16(v, h, l);
        Th[(size_t)n * K + k] = h;
        Tl[(size_t)n * K + k] = l;
    }
}

// ==================== fp32 -> bf16 pair ====================================
__global__ void pairify_kernel(const float* __restrict__ src,
                               bf16* __restrict__ h, bf16* __restrict__ l, int n)
{
    int idx = blockIdx.x * blockDim.x + threadIdx.x;
    if (idx >= n) return;
    bf16 hh, ll;
    split_bf16(src[idx], hh, ll);
    h[idx] = hh; l[idx] = ll;
}

// ==================== quality gating =======================================
__global__ void gate_kernel(const float* __restrict__ x,
                            const float* __restrict__ u,
                            const float* __restrict__ alpha,
                            const float* __restrict__ b_delta)
{
    int idx = blockIdx.x * blockDim.x + threadIdx.x;
    if (idx >= BT * DM) return;
    int r = idx / DM, c = idx % DM;
    float v        = g_tmp[idx] + b_delta[c];
    float draw     = softplusf(v);
    float delta_id = draw * expf(-alpha[0] * u[r]);
    float gate     = delta_id / (1.f + delta_id);
    float xgv = x[idx] * gate;
    bf16 h, l;
    split_bf16(xgv, h, l);
    g_xgh[idx] = h; g_xgl[idx] = l;
}

// ==================== causal depthwise conv + silu (both dirs via z) =======
__global__ void conv_kernel(const float* __restrict__ cw0, const float* __restrict__ cb0,
                            const float* __restrict__ cw1, const float* __restrict__ cb1)
{
    int idx = blockIdx.x * blockDim.x + threadIdx.x;
    if (idx >= BT * DI) return;
    const int dir = blockIdx.z;
    const float* cw = dir ? cw1 : cw0;
    const float* cb = dir ? cb1 : cb0;
    int r = idx / DI, c = idx % DI;
    int t = r % TLEN;
    const float* xzp = g_xz[dir];
    float acc = cb[c];
#pragma unroll
    for (int k = 0; k < 4; k++) {
        int ts = t - 3 + k;
        if (ts >= 0)
            acc = fmaf(cw[c * 4 + k], xzp[(size_t)(r - 3 + k) * (2 * DI) + c], acc);
    }
    float v = acc / (1.f + __expf(-acc));
    g_xc[dir][idx] = v;
    bf16 h, l;
    split_bf16(v, h, l);
    g_xch[dir][idx] = h; g_xcl[dir][idx] = l;
}

// ==================== selective scan (state-split + prefetch) ==============
// grid (DI/64, BSZ, 2), block 128. lane pair: tid&1 -> states [0..7]/[8..15]
__global__ __launch_bounds__(128)
void scan_kernel(const float* __restrict__ Af, const float* __restrict__ Dpf,
                 const float* __restrict__ Ab, const float* __restrict__ Dpb)
{
    const int dir = blockIdx.z;
    const int b   = blockIdx.y;
    const int tid = threadIdx.x;
    const int ch  = blockIdx.x * 64 + (tid >> 1);
    const int sh  = (tid & 1) * 8;

    const float* Alog = dir ? Ab  : Af;
    const float* Dp   = dir ? Dpb : Dpf;

    float a[8], h[8];
#pragma unroll
    for (int s = 0; s < 8; s++) {
        a[s] = -expf(Alog[ch * DS + sh + s]);
        h[s] = 0.f;
    }
    const float dpv = Dp[ch];

    const float* dtp  = g_dt[dir];
    const float* xcp  = g_xc[dir];
    const float* xzp  = g_xz[dir];
    const float* xdbp = g_xdb[dir];
    bf16* yh = g_yh[dir];
    bf16* yl = g_yl[dir];

    size_t base = (size_t)b * TLEN * DI + ch;
    size_t xzi  = (size_t)b * TLEN * (2 * DI) + DI + ch;
    size_t xdbi = (size_t)b * TLEN * XDBW + DTR + sh;

    float dtv = dtp[base], xcv = xcp[base], zv = xzp[xzi];
    float4 B0 = __ldg((const float4*)(xdbp + xdbi));
    float4 B1 = __ldg((const float4*)(xdbp + xdbi + 4));
    float4 C0 = __ldg((const float4*)(xdbp + xdbi + DS));
    float4 C1 = __ldg((const float4*)(xdbp + xdbi + DS + 4));

    for (int t = 0; t < TLEN; t++) {
        float dtn = 0.f, xcn = 0.f, zn = 0.f;
        float4 B0n = B0, B1n = B1, C0n = C0, C1n = C1;
        if (t + 1 < TLEN) {
            size_t b2 = base + DI, x2 = xzi + 2 * DI, d2 = xdbi + XDBW;
            dtn = dtp[b2]; xcn = xcp[b2]; zn = xzp[x2];
            B0n = __ldg((const float4*)(xdbp + d2));
            B1n = __ldg((const float4*)(xdbp + d2 + 4));
            C0n = __ldg((const float4*)(xdbp + d2 + DS));
            C1n = __ldg((const float4*)(xdbp + d2 + DS + 4));
        }

        float Bv[8] = {B0.x, B0.y, B0.z, B0.w, B1.x, B1.y, B1.z, B1.w};
        float Cv[8] = {C0.x, C0.y, C0.z, C0.w, C1.x, C1.y, C1.z, C1.w};
        float dtx  = dtv * xcv;
        float ysum = 0.f;
#pragma unroll
        for (int s = 0; s < 8; s++) {
            float dA = __expf(dtv * a[s]);
            h[s] = fmaf(dA, h[s], dtx * Bv[s]);
            ysum = fmaf(h[s], Cv[s], ysum);
        }
        ysum += __shfl_xor_sync(0xFFFFFFFFu, ysum, 1);
        if ((tid & 1) == 0) {
            float sz = zv / (1.f + __expf(-zv));
            float yv = (ysum + xcv * dpv) * sz;
            bf16 hh, ll;
            split_bf16(yv, hh, ll);
            yh[base] = hh; yl[base] = ll;
        }

        base += DI; xzi += 2 * DI; xdbi += XDBW;
        dtv = dtn; xcv = xcn; zv = zn;
        B0 = B0n; B1 = B1n; C0 = C0n; C1 = C1n;
    }
}

// ==================== host driver ==========================================
static inline dim3 ggrid(int M, int N, int nz) {
    return dim3((N + 127) / 128, M / 128, nz);
}

extern "C" void kernel_launch(void* const* d_in, const int* in_sizes, int n_in,
                              void* d_out, int out_size)
{
    const float* x       = (const float*)d_in[0];
    const float* u       = (const float*)d_in[1];
    const float* alpha   = (const float*)d_in[2];
    const float* W_delta = (const float*)d_in[3];
    const float* b_delta = (const float*)d_in[4];
    const float* W_proj  = (const float*)d_in[5];
    const float* b_proj  = (const float*)d_in[6];

    const float* W_in[2]   = {(const float*)d_in[7],  (const float*)d_in[16]};
    const float* conv_w[2] = {(const float*)d_in[8],  (const float*)d_in[17]};
    const float* conv_b[2] = {(const float*)d_in[9],  (const float*)d_in[18]};
    const float* W_x[2]    = {(const float*)d_in[10], (const float*)d_in[19]};
    const float* W_dt[2]   = {(const float*)d_in[11], (const float*)d_in[20]};
    const float* b_dt[2]   = {(const float*)d_in[12], (const float*)d_in[21]};
    const float* A_log[2]  = {(const float*)d_in[13], (const float*)d_in[22]};
    const float* Dp[2]     = {(const float*)d_in[14], (const float*)d_in[23]};
    const float* W_out[2]  = {(const float*)d_in[15], (const float*)d_in[24]};

    float* out     = (float*)d_out;
    float* fwd_out = out + (size_t)BT * DM;

    float *tmp, *xz, *xdb, *dt;
    cudaGetSymbolAddress((void**)&tmp, g_tmp);
    cudaGetSymbolAddress((void**)&xz,  g_xz);
    cudaGetSymbolAddress((void**)&xdb, g_xdb);
    cudaGetSymbolAddress((void**)&dt,  g_dt);

    bf16 *xh, *xl, *xgh, *xgl, *xch, *xcl, *dlh, *dll, *yh, *yl, *opch, *opcl;
    cudaGetSymbolAddress((void**)&xh,  g_xh);   cudaGetSymbolAddress((void**)&xl,  g_xl);
    cudaGetSymbolAddress((void**)&xgh, g_xgh);  cudaGetSymbolAddress((void**)&xgl, g_xgl);
    cudaGetSymbolAddress((void**)&xch, g_xch);  cudaGetSymbolAddress((void**)&xcl, g_xcl);
    cudaGetSymbolAddress((void**)&dlh, g_dlh);  cudaGetSymbolAddress((void**)&dll, g_dll);
    cudaGetSymbolAddress((void**)&yh,  g_yh);   cudaGetSymbolAddress((void**)&yl,  g_yl);
    cudaGetSymbolAddress((void**)&opch, g_opch); cudaGetSymbolAddress((void**)&opcl, g_opcl);

    bf16 *WdTh, *WdTl, *WinTh, *WinTl, *WxTh, *WxTl, *WdtTh, *WdtTl, *WoTh, *WoTl, *WpTh, *WpTl;
    cudaGetSymbolAddress((void**)&WdTh,  g_WdTh);  cudaGetSymbolAddress((void**)&WdTl,  g_WdTl);
    cudaGetSymbolAddress((void**)&WinTh, g_WinTh); cudaGetSymbolAddress((void**)&WinTl, g_WinTl);
    cudaGetSymbolAddress((void**)&WxTh,  g_WxTh);  cudaGetSymbolAddress((void**)&WxTl,  g_WxTl);
    cudaGetSymbolAddress((void**)&WdtTh, g_WdtTh); cudaGetSymbolAddress((void**)&WdtTl, g_WdtTl);
    cudaGetSymbolAddress((void**)&WoTh,  g_WoTh);  cudaGetSymbolAddress((void**)&WoTl,  g_WoTl);
    cudaGetSymbolAddress((void**)&WpTh,  g_WpTh);  cudaGetSymbolAddress((void**)&WpTl,  g_WpTl);

    cudaFuncSetAttribute(tcgemm, cudaFuncAttributeMaxDynamicSharedMemorySize, GEMM_SMEM);

    const long long XZ_S  = (long long)BT * 2 * DI;
    const long long XC_S  = (long long)BT * DI;
    const long long XDB_S = (long long)BT * XDBW;
    const long long DL_S  = (long long)BT * DTR;
    const long long OP_S  = (long long)BT * DM;
    const long long WIN_S = (long long)4 * DM * DM;
    const long long WX_S  = (long long)128 * DI;
    const long long WDT_S = (long long)DI * DTR;
    const long long WO_S  = (long long)DM * DI;

    dim3 tb(32, 8);
    wtrans_kernel<<<dim3(DM / 32, DM / 32), tb>>>(W_delta, WdTh, WdTl, DM, DM);
    wtrans_kernel<<<dim3((2 * DM) / 32, DM / 32), tb>>>(W_proj, WpTh, WpTl, 2 * DM, DM);
    for (int d2 = 0; d2 < 2; d2++) {
        wtrans_kernel<<<dim3(DM / 32, (4 * DM) / 32), tb>>>(W_in[d2],  WinTh + d2 * WIN_S, WinTl + d2 * WIN_S, DM, 4 * DM);
        wtrans_kernel<<<dim3(DI / 32, 128 / 32), tb>>>(W_x[d2],   WxTh  + d2 * WX_S,  WxTl  + d2 * WX_S,  DI, XDBW);
        wtrans_kernel<<<dim3(DTR / 32, DI / 32), tb>>>(W_dt[d2],  WdtTh + d2 * WDT_S, WdtTl + d2 * WDT_S, DTR, DI);
        wtrans_kernel<<<dim3(DI / 32, DM / 32), tb>>>(W_out[d2],  WoTh  + d2 * WO_S,  WoTl  + d2 * WO_S,  DI, DM);
    }
    pairify_kernel<<<(BT * DM + 255) / 256, 256>>>(x, xh, xl, BT * DM);

    // 1) tmp = x @ W_delta
    tcgemm<<<ggrid(BT, DM, 1), 256, GEMM_SMEM>>>(
        xh, xl, WdTh, WdTl, tmp, nullptr, nullptr, nullptr, nullptr,
        BT, DM, DM, DM, 0, 0, 0, 0, 0, 0, 0, 0);
    // 2) gate -> xg pair
    gate_kernel<<<(BT * DM + 255) / 256, 256>>>(x, u, alpha, b_delta);

    // 3) xz = xg @ W_in  (both dirs; bwd flips A rows)
    tcgemm<<<ggrid(BT, 4 * DM, 2), 256, GEMM_SMEM>>>(
        xgh, xgl, WinTh, WinTl, xz, nullptr, nullptr, nullptr, nullptr,
        BT, 4 * DM, DM, 4 * DM, 0, 0, 0, WIN_S, XZ_S, 0, 0, F_FLIPA);

    // 4) conv + silu (both dirs)
    conv_kernel<<<dim3((BT * DI + 255) / 256, 1, 2), 256>>>(
        conv_w[0], conv_b[0], conv_w[1], conv_b[1]);

    // 5) xdb = xc @ W_x  (+pair of first 64 cols -> dt_lo pair), both dirs
    tcgemm<<<ggrid(BT, XDBW, 2), 256, GEMM_SMEM>>>(
        xch, xcl, WxTh, WxTl, xdb, nullptr, nullptr, dlh, dll,
        BT, XDBW, DI, XDBW, DTR, DTR, XC_S, WX_S, XDB_S, DL_S, F_PAIR, F_PAIR);

    // 6) dt = softplus(dt_lo @ W_dt + b_dt), both dirs
    tcgemm<<<ggrid(BT, DI, 2), 256, GEMM_SMEM>>>(
        dlh, dll, WdtTh, WdtTl, dt, b_dt[0], b_dt[1], nullptr, nullptr,
        BT, DI, DTR, DI, 0, 0, DL_S, WDT_S, XC_S, 0, F_BIAS | F_SP, F_BIAS | F_SP);

    // 7) selective scan -> y pair
    scan_kernel<<<dim3(DI / 64, BSZ, 2), 128>>>(A_log[0], Dp[0], A_log[1], Dp[1]);

    // 8) out_dir = y @ W_out (both dirs; bwd flips C rows); pairs into concat buf
    tcgemm<<<ggrid(BT, DM, 2), 256, GEMM_SMEM>>>(
        yh, yl, WoTh, WoTl, fwd_out, nullptr, nullptr, opch, opcl,
        BT, DM, DI, DM, DM, 2 * DM, XC_S, WO_S, OP_S, DM,
        F_PAIR, F_PAIR | F_FLIPC);

    // 9) out = [fwd|bwd] @ W_proj + b_proj   (single K=2048 GEMM)
    tcgemm<<<ggrid(BT, DM, 1), 256, GEMM_SMEM>>>(
        opch, opcl, WpTh, WpTl, out, b_proj, nullptr, nullptr, nullptr,
        BT, DM, 2 * DM, DM, 0, 0, 0, 0, 0, 0, F_BIAS, F_BIAS);
}

// round 10
// speedup vs baseline: 2.1350x; 1.0117x over previous
#include <cuda_runtime.h>
#include <cuda_bf16.h>
#include <math.h>
#include <stdint.h>

#define BSZ   2
#define TLEN  2048
#define DM    1024
#define DI    2048
#define DS    16
#define DTR   64
#define BT    4096     // BSZ*TLEN
#define XDBW  96       // DTR + 2*DS

// epilogue flags
#define F_FLIPA 1
#define F_FLIPC 2
#define F_ACC   4
#define F_BIAS  8
#define F_SP    16
#define F_PAIR  32
#define F_GATE  64

typedef __nv_bfloat16 bf16;

// ==================== scratch (device globals) =============================
__device__ float g_xz [2][BT * (2 * DI)];        // per-dir [xi | z]
__device__ float g_xc [2][BT * DI];              // conv+silu output (fp32, for scan)
__device__ float g_xdb[2][BT * XDBW];            // [dt_lo | B | C]
__device__ float g_dt [2][BT * DI];              // softplus(dt)

// bf16 split pairs (activations)
__device__ bf16 g_xh [BT * DM],  g_xl [BT * DM];
__device__ bf16 g_xgh[BT * DM],  g_xgl[BT * DM];
__device__ bf16 g_xch[2][BT * DI], g_xcl[2][BT * DI];
__device__ bf16 g_dlh[2][BT * DTR], g_dll[2][BT * DTR];
__device__ bf16 g_yh [2][BT * DI], g_yl [2][BT * DI];
__device__ bf16 g_opch[BT * 2 * DM], g_opcl[BT * 2 * DM];  // concat fwd|bwd

// bf16 split pairs (transposed weights, [N,K] K-major)
__device__ bf16 g_WdTh[DM * DM],        g_WdTl[DM * DM];
__device__ bf16 g_WinTh[2][4 * DM * DM], g_WinTl[2][4 * DM * DM];
__device__ bf16 g_WxTh[2][128 * DI],    g_WxTl[2][128 * DI];   // padded N=128
__device__ bf16 g_WdtTh[2][DI * DTR],   g_WdtTl[2][DI * DTR];
__device__ bf16 g_WoTh[2][DM * DI],     g_WoTl[2][DM * DI];
__device__ bf16 g_WpTh[DM * 2 * DM],    g_WpTl[DM * 2 * DM];   // [1024, 2048]

// ==================== helpers ==============================================
__device__ __forceinline__ uint32_t smem_u32(const void* p) {
    uint32_t a;
    asm("{ .reg .u64 t; cvta.to.shared.u64 t, %1; cvt.u32.u64 %0, t; }"
        : "=r"(a) : "l"(p));
    return a;
}
__device__ __forceinline__ float softplusf(float v) {
    return v > 20.f ? v : log1pf(expf(v));
}
__device__ __forceinline__ void split_bf16(float v, bf16& h, bf16& l) {
    h = __float2bfloat16(v);
    l = __float2bfloat16(v - __bfloat162float(h));
}
__device__ __forceinline__ void cp16(uint32_t s, const void* g) {
    asm volatile("cp.async.cg.shared.global [%0], [%1], 16;" :: "r"(s), "l"(g) : "memory");
}
__device__ __forceinline__ void cp_commit() {
    asm volatile("cp.async.commit_group;" ::: "memory");
}
template <int N> __device__ __forceinline__ void cp_wait() {
    asm volatile("cp.async.wait_group %0;" :: "n"(N) : "memory");
}
__device__ __forceinline__ void ldm_x4(uint32_t* r, uint32_t addr) {
    asm volatile("ldmatrix.sync.aligned.m8n8.x4.shared.b16 {%0,%1,%2,%3}, [%4];"
                 : "=r"(r[0]), "=r"(r[1]), "=r"(r[2]), "=r"(r[3]) : "r"(addr));
}
__device__ __forceinline__ void mma16816(float* c, const uint32_t* a, uint32_t b0, uint32_t b1) {
    asm volatile(
        "mma.sync.aligned.m16n8k16.row.col.f32.bf16.bf16.f32 "
        "{%0,%1,%2,%3}, {%4,%5,%6,%7}, {%8,%9}, {%0,%1,%2,%3};"
        : "+f"(c[0]), "+f"(c[1]), "+f"(c[2]), "+f"(c[3])
        : "r"(a[0]), "r"(a[1]), "r"(a[2]), "r"(a[3]), "r"(b0), "r"(b1));
}

// ==================== HMMA GEMM ============================================
// C[M,N] = (Ah+Al)[M,K] @ (Bh+Bl)[N,K]^T   (3 split terms: hh + hl + lh)
// 128x128 tile, BK=32, 8 warps x (32m x 64n), 4-stage cp.async pipeline,
// one __syncthreads per chunk, fragment double-buffer across kk.
#define KSTRIDE  80
#define TILE_B   (128 * KSTRIDE)          // 10240
#define STAGE_B  (4 * TILE_B)             // 40960
#define GEMM_SMEM (4 * STAGE_B)           // 163840

__global__ __launch_bounds__(256)
void tcgemm(const bf16* __restrict__ Ah, const bf16* __restrict__ Al,
            const bf16* __restrict__ Bh, const bf16* __restrict__ Bl,
            float* __restrict__ C, const float* __restrict__ bias0,
            const float* __restrict__ bias1,
            bf16* __restrict__ Ph, bf16* __restrict__ Pl,
            const float* __restrict__ gx, const float* __restrict__ gu,
            const float* __restrict__ gal,
            int M, int N, int K, int ldc, int pairN, int pairLd,
            long long sA, long long sB, long long sC, long long sP,
            int flags0, int flags1)
{
    extern __shared__ __align__(128) char smem[];
    const uint32_t sbase = smem_u32(smem);
    const int z = blockIdx.z;
    const int flags = z ? flags1 : flags0;
    const float* bias = z ? bias1 : bias0;
    Ah += z * sA; Al += z * sA;
    Bh += z * sB; Bl += z * sB;
    C  += z * sC;
    const long long poff = (long long)z * sP;

    const int tid  = threadIdx.x;
    const int lane = tid & 31;
    const int wid  = tid >> 5;
    const int warp_m = wid >> 1;      // 0..3
    const int warp_n = wid & 1;       // 0..1
    const int bm = blockIdx.y * 128;
    const int bn = blockIdx.x * 128;

    // ---- load geometry ----
    size_t   a_goff[2], b_goff[2];
    uint32_t s_off[2];
#pragma unroll
    for (int i = 0; i < 2; i++) {
        int row = (tid + i * 256) >> 2;
        int seg = tid & 3;
        int am = bm + row;
        if (flags & F_FLIPA) { int b_ = am / TLEN, t_ = am % TLEN; am = b_ * TLEN + (TLEN - 1 - t_); }
        a_goff[i] = ((size_t)am * K + seg * 8) * 2;
        b_goff[i] = ((size_t)(bn + row) * K + seg * 8) * 2;
        s_off[i]  = row * KSTRIDE + seg * 16;
    }

    const int a_lm_row = lane & 15;
    const int a_lm_cb  = (lane >> 4) * 16;
    const int b_lm_row = (lane & 7) + ((lane >> 4) & 1) * 8;
    const int b_lm_cb  = ((lane >> 3) & 1) * 16;
    const uint32_t a_pre = (warp_m * 32 + a_lm_row) * KSTRIDE + a_lm_cb;
    const uint32_t b_pre = (warp_n * 64 + b_lm_row) * KSTRIDE + b_lm_cb;

    float acc[2][8][4];
#pragma unroll
    for (int mt = 0; mt < 2; mt++)
#pragma unroll
        for (int nt = 0; nt < 8; nt++)
#pragma unroll
            for (int q = 0; q < 4; q++) acc[mt][nt][q] = 0.f;

    const int NC = K / 32;

#define ISSUE(cc) do {                                                        \
        uint32_t sb = sbase + ((cc) & 3) * STAGE_B;                           \
        size_t cbv = (size_t)(cc) * 64;                                       \
        _Pragma("unroll")                                                     \
        for (int i = 0; i < 2; i++) {                                         \
            cp16(sb +            s_off[i], (const char*)Ah + a_goff[i] + cbv);\
            cp16(sb + TILE_B   + s_off[i], (const char*)Al + a_goff[i] + cbv);\
            cp16(sb + 2*TILE_B + s_off[i], (const char*)Bh + b_goff[i] + cbv);\
            cp16(sb + 3*TILE_B + s_off[i], (const char*)Bl + b_goff[i] + cbv);\
        }                                                                     \
        cp_commit();                                                          \
    } while (0)

// load ldmatrix fragments for one 16-wide k-step into buffer `bb`
#define LOADF(bb, st, kb) do {                                                \
        _Pragma("unroll")                                                     \
        for (int mt = 0; mt < 2; mt++) {                                      \
            ldm_x4(a_h[bb][mt], (st) +          a_pre + mt * 16 * KSTRIDE + (kb)); \
            ldm_x4(a_l[bb][mt], (st) + TILE_B + a_pre + mt * 16 * KSTRIDE + (kb)); \
        }                                                                     \
        _Pragma("unroll")                                                     \
        for (int p = 0; p < 4; p++) {                                         \
            uint32_t r_[4];                                                   \
            ldm_x4(r_, (st) + 2*TILE_B + b_pre + p * 16 * KSTRIDE + (kb));    \
            b_h[bb][2*p][0] = r_[0]; b_h[bb][2*p][1] = r_[1];                 \
            b_h[bb][2*p+1][0] = r_[2]; b_h[bb][2*p+1][1] = r_[3];             \
            ldm_x4(r_, (st) + 3*TILE_B + b_pre + p * 16 * KSTRIDE + (kb));    \
            b_l[bb][2*p][0] = r_[0]; b_l[bb][2*p][1] = r_[1];                 \
            b_l[bb][2*p+1][0] = r_[2]; b_l[bb][2*p+1][1] = r_[3];             \
        }                                                                     \
    } while (0)

    int issued = NC < 3 ? NC : 3;
    for (int c = 0; c < issued; c++) ISSUE(c);

    uint32_t a_h[2][2][4], a_l[2][2][4];
    uint32_t b_h[2][8][2], b_l[2][8][2];

    for (int c = 0; c < NC; c++) {
        int rem = issued - c - 1;
        if (rem >= 2) cp_wait<2>();
        else if (rem == 1) cp_wait<1>();
        else cp_wait<0>();
        __syncthreads();

        if (issued < NC) { ISSUE(issued); issued++; }

        const uint32_t st = sbase + (c & 3) * STAGE_B;
        LOADF(0, st, 0);
#pragma unroll
        for (int kk = 0; kk < 2; kk++) {
            if (kk == 0) LOADF(1, st, 32);
            // three passes: each accumulator touched once per pass (no RAW chain)
#pragma unroll
            for (int mt = 0; mt < 2; mt++)
#pragma unroll
                for (int nt = 0; nt < 8; nt++)
                    mma16816(acc[mt][nt], a_h[kk][mt], b_h[kk][nt][0], b_h[kk][nt][1]);
#pragma unroll
            for (int mt = 0; mt < 2; mt++)
#pragma unroll
                for (int nt = 0; nt < 8; nt++)
                    mma16816(acc[mt][nt], a_h[kk][mt], b_l[kk][nt][0], b_l[kk][nt][1]);
#pragma unroll
            for (int mt = 0; mt < 2; mt++)
#pragma unroll
                for (int nt = 0; nt < 8; nt++)
                    mma16816(acc[mt][nt], a_l[kk][mt], b_h[kk][nt][0], b_h[kk][nt][1]);
        }
    }
#undef ISSUE
#undef LOADF

    // ---- epilogue ----
    const int row_in = lane >> 2;
    const int col_in = (lane & 3) * 2;
#pragma unroll
    for (int mt = 0; mt < 2; mt++) {
#pragma unroll
        for (int half = 0; half < 2; half++) {
            int gm = bm + warp_m * 32 + mt * 16 + row_in + half * 8;
            int gmp = gm;
            if (flags & F_FLIPC) { int b_ = gm / TLEN, t_ = gm % TLEN; gmp = b_ * TLEN + (TLEN - 1 - t_); }
#pragma unroll
            for (int nt = 0; nt < 8; nt++) {
                int gn = bn + warp_n * 64 + nt * 8 + col_in;
                if (gn >= N) continue;
                float v0 = acc[mt][nt][half * 2 + 0];
                float v1 = acc[mt][nt][half * 2 + 1];
                size_t ci = (size_t)gmp * ldc + gn;
                if (flags & F_ACC)  { v0 += C[ci]; v1 += C[ci + 1]; }
                if (flags & F_BIAS) { v0 += bias[gn]; v1 += bias[gn + 1]; }
                if (flags & F_SP)   { v0 = softplusf(v0); v1 = softplusf(v1); }
                if (flags & F_GATE) {
                    // v = softplus(x@Wd + b) already; apply exp(-alpha*u) gate, mult x
                    float e = __expf(-gal[0] * gu[gmp]);
                    float d0 = v0 * e, d1 = v1 * e;
                    float g0 = d0 / (1.f + d0), g1 = d1 / (1.f + d1);
                    size_t xi = (size_t)gmp * pairLd + gn;
                    float xg0 = gx[xi] * g0, xg1 = gx[xi + 1] * g1;
                    size_t pi = (size_t)(poff + (long long)gmp * pairLd + gn);
                    bf16 h, l;
                    split_bf16(xg0, h, l); Ph[pi] = h;     Pl[pi] = l;
                    split_bf16(xg1, h, l); Ph[pi + 1] = h; Pl[pi + 1] = l;
                } else {
                    C[ci]     = v0;
                    C[ci + 1] = v1;
                    if ((flags & F_PAIR) && gn < pairN) {
                        size_t pi = (size_t)(poff + (long long)gmp * pairLd + gn);
                        bf16 h, l;
                        split_bf16(v0, h, l); Ph[pi] = h;     Pl[pi] = l;
                        split_bf16(v1, h, l); Ph[pi + 1] = h; Pl[pi + 1] = l;
                    }
                }
            }
        }
    }
}

// ==================== transpose + bf16-split weights =======================
__global__ void wtrans_kernel(const float* __restrict__ W,
                              bf16* __restrict__ Th, bf16* __restrict__ Tl,
                              int K, int N)
{
    __shared__ float tile[32][33];
    int k0 = blockIdx.x * 32, n0 = blockIdx.y * 32;
    int tx = threadIdx.x, ty = threadIdx.y;   // 32 x 8
#pragma unroll
    for (int i = 0; i < 32; i += 8) {
        int k = k0 + ty + i, n = n0 + tx;
        tile[ty + i][tx] = (n < N) ? W[(size_t)k * N + n] : 0.f;
    }
    __syncthreads();
#pragma unroll
    for (int i = 0; i < 32; i += 8) {
        int n = n0 + ty + i, k = k0 + tx;
        float v = tile[tx][ty + i];
        bf16 h, l;
        split_bf16(v, h, l);
        Th[(size_t)n * K + k] = h;
        Tl[(size_t)n * K + k] = l;
    }
}

// ==================== fp32 -> bf16 pair ====================================
__global__ void pairify_kernel(const float* __restrict__ src,
                               bf16* __restrict__ h, bf16* __restrict__ l, int n)
{
    int idx = blockIdx.x * blockDim.x + threadIdx.x;
    if (idx >= n) return;
    bf16 hh, ll;
    split_bf16(src[idx], hh, ll);
    h[idx] = hh; l[idx] = ll;
}

// ==================== causal depthwise conv + silu (both dirs via z) =======
__global__ void conv_kernel(const float* __restrict__ cw0, const float* __restrict__ cb0,
                            const float* __restrict__ cw1, const float* __restrict__ cb1)
{
    int idx = blockIdx.x * blockDim.x + threadIdx.x;
    if (idx >= BT * DI) return;
    const int dir = blockIdx.z;
    const float* cw = dir ? cw1 : cw0;
    const float* cb = dir ? cb1 : cb0;
    int r = idx / DI, c = idx % DI;
    int t = r % TLEN;
    const float* xzp = g_xz[dir];
    float acc = cb[c];
#pragma unroll
    for (int k = 0; k < 4; k++) {
        int ts = t - 3 + k;
        if (ts >= 0)
            acc = fmaf(cw[c * 4 + k], xzp[(size_t)(r - 3 + k) * (2 * DI) + c], acc);
    }
    float v = acc / (1.f + __expf(-acc));
    g_xc[dir][idx] = v;
    bf16 h, l;
    split_bf16(v, h, l);
    g_xch[dir][idx] = h; g_xcl[dir][idx] = l;
}

// ==================== selective scan (state-split + prefetch) ==============
__global__ __launch_bounds__(128)
void scan_kernel(const float* __restrict__ Af, const float* __restrict__ Dpf,
                 const float* __restrict__ Ab, const float* __restrict__ Dpb)
{
    const int dir = blockIdx.z;
    const int b   = blockIdx.y;
    const int tid = threadIdx.x;
    const int ch  = blockIdx.x * 64 + (tid >> 1);
    const int sh  = (tid & 1) * 8;

    const float* Alog = dir ? Ab  : Af;
    const float* Dp   = dir ? Dpb : Dpf;

    float a[8], h[8];
#pragma unroll
    for (int s = 0; s < 8; s++) {
        a[s] = -expf(Alog[ch * DS + sh + s]);
        h[s] = 0.f;
    }
    const float dpv = Dp[ch];

    const float* dtp  = g_dt[dir];
    const float* xcp  = g_xc[dir];
    const float* xzp  = g_xz[dir];
    const float* xdbp = g_xdb[dir];
    bf16* yh = g_yh[dir];
    bf16* yl = g_yl[dir];

    size_t base = (size_t)b * TLEN * DI + ch;
    size_t xzi  = (size_t)b * TLEN * (2 * DI) + DI + ch;
    size_t xdbi = (size_t)b * TLEN * XDBW + DTR + sh;

    float dtv = dtp[base], xcv = xcp[base], zv = xzp[xzi];
    float4 B0 = __ldg((const float4*)(xdbp + xdbi));
    float4 B1 = __ldg((const float4*)(xdbp + xdbi + 4));
    float4 C0 = __ldg((const float4*)(xdbp + xdbi + DS));
    float4 C1 = __ldg((const float4*)(xdbp + xdbi + DS + 4));

    for (int t = 0; t < TLEN; t++) {
        float dtn = 0.f, xcn = 0.f, zn = 0.f;
        float4 B0n = B0, B1n = B1, C0n = C0, C1n = C1;
        if (t + 1 < TLEN) {
            size_t b2 = base + DI, x2 = xzi + 2 * DI, d2 = xdbi + XDBW;
            dtn = dtp[b2]; xcn = xcp[b2]; zn = xzp[x2];
            B0n = __ldg((const float4*)(xdbp + d2));
            B1n = __ldg((const float4*)(xdbp + d2 + 4));
            C0n = __ldg((const float4*)(xdbp + d2 + DS));
            C1n = __ldg((const float4*)(xdbp + d2 + DS + 4));
        }

        float Bv[8] = {B0.x, B0.y, B0.z, B0.w, B1.x, B1.y, B1.z, B1.w};
        float Cv[8] = {C0.x, C0.y, C0.z, C0.w, C1.x, C1.y, C1.z, C1.w};
        float dtx  = dtv * xcv;
        float ysum = 0.f;
#pragma unroll
        for (int s = 0; s < 8; s++) {
            float dA = __expf(dtv * a[s]);
            h[s] = fmaf(dA, h[s], dtx * Bv[s]);
            ysum = fmaf(h[s], Cv[s], ysum);
        }
        ysum += __shfl_xor_sync(0xFFFFFFFFu, ysum, 1);
        if ((tid & 1) == 0) {
            float sz = zv / (1.f + __expf(-zv));
            float yv = (ysum + xcv * dpv) * sz;
            bf16 hh, ll;
            split_bf16(yv, hh, ll);
            yh[base] = hh; yl[base] = ll;
        }

        base += DI; xzi += 2 * DI; xdbi += XDBW;
        dtv = dtn; xcv = xcn; zv = zn;
        B0 = B0n; B1 = B1n; C0 = C0n; C1 = C1n;
    }
}

// ==================== host driver ==========================================
static inline dim3 ggrid(int M, int N, int nz) {
    return dim3((N + 127) / 128, M / 128, nz);
}

extern "C" void kernel_launch(void* const* d_in, const int* in_sizes, int n_in,
                              void* d_out, int out_size)
{
    const float* x       = (const float*)d_in[0];
    const float* u       = (const float*)d_in[1];
    const float* alpha   = (const float*)d_in[2];
    const float* W_delta = (const float*)d_in[3];
    const float* b_delta = (const float*)d_in[4];
    const float* W_proj  = (const float*)d_in[5];
    const float* b_proj  = (const float*)d_in[6];

    const float* W_in[2]   = {(const float*)d_in[7],  (const float*)d_in[16]};
    const float* conv_w[2] = {(const float*)d_in[8],  (const float*)d_in[17]};
    const float* conv_b[2] = {(const float*)d_in[9],  (const float*)d_in[18]};
    const float* W_x[2]    = {(const float*)d_in[10], (const float*)d_in[19]};
    const float* W_dt[2]   = {(const float*)d_in[11], (const float*)d_in[20]};
    const float* b_dt[2]   = {(const float*)d_in[12], (const float*)d_in[21]};
    const float* A_log[2]  = {(const float*)d_in[13], (const float*)d_in[22]};
    const float* Dp[2]     = {(const float*)d_in[14], (const float*)d_in[23]};
    const float* W_out[2]  = {(const float*)d_in[15], (const float*)d_in[24]};

    float* out     = (float*)d_out;
    float* fwd_out = out + (size_t)BT * DM;

    float *xz, *xdb, *dt;
    cudaGetSymbolAddress((void**)&xz,  g_xz);
    cudaGetSymbolAddress((void**)&xdb, g_xdb);
    cudaGetSymbolAddress((void**)&dt,  g_dt);

    bf16 *xh, *xl, *xgh, *xgl, *xch, *xcl, *dlh, *dll, *yh, *yl, *opch, *opcl;
    cudaGetSymbolAddress((void**)&xh,  g_xh);   cudaGetSymbolAddress((void**)&xl,  g_xl);
    cudaGetSymbolAddress((void**)&xgh, g_xgh);  cudaGetSymbolAddress((void**)&xgl, g_xgl);
    cudaGetSymbolAddress((void**)&xch, g_xch);  cudaGetSymbolAddress((void**)&xcl, g_xcl);
    cudaGetSymbolAddress((void**)&dlh, g_dlh);  cudaGetSymbolAddress((void**)&dll, g_dll);
    cudaGetSymbolAddress((void**)&yh,  g_yh);   cudaGetSymbolAddress((void**)&yl,  g_yl);
    cudaGetSymbolAddress((void**)&opch, g_opch); cudaGetSymbolAddress((void**)&opcl, g_opcl);

    bf16 *WdTh, *WdTl, *WinTh, *WinTl, *WxTh, *WxTl, *WdtTh, *WdtTl, *WoTh, *WoTl, *WpTh, *WpTl;
    cudaGetSymbolAddress((void**)&WdTh,  g_WdTh);  cudaGetSymbolAddress((void**)&WdTl,  g_WdTl);
    cudaGetSymbolAddress((void**)&WinTh, g_WinTh); cudaGetSymbolAddress((void**)&WinTl, g_WinTl);
    cudaGetSymbolAddress((void**)&WxTh,  g_WxTh);  cudaGetSymbolAddress((void**)&WxTl,  g_WxTl);
    cudaGetSymbolAddress((void**)&WdtTh, g_WdtTh); cudaGetSymbolAddress((void**)&WdtTl, g_WdtTl);
    cudaGetSymbolAddress((void**)&WoTh,  g_WoTh);  cudaGetSymbolAddress((void**)&WoTl,  g_WoTl);
    cudaGetSymbolAddress((void**)&WpTh,  g_WpTh);  cudaGetSymbolAddress((void**)&WpTl,  g_WpTl);

    cudaFuncSetAttribute(tcgemm, cudaFuncAttributeMaxDynamicSharedMemorySize, GEMM_SMEM);

    const long long XZ_S  = (long long)BT * 2 * DI;
    const long long XC_S  = (long long)BT * DI;
    const long long XDB_S = (long long)BT * XDBW;
    const long long DL_S  = (long long)BT * DTR;
    const long long OP_S  = (long long)BT * DM;
    const long long WIN_S = (long long)4 * DM * DM;
    const long long WX_S  = (long long)128 * DI;
    const long long WDT_S = (long long)DI * DTR;
    const long long WO_S  = (long long)DM * DI;

    dim3 tb(32, 8);
    wtrans_kernel<<<dim3(DM / 32, DM / 32), tb>>>(W_delta, WdTh, WdTl, DM, DM);
    wtrans_kernel<<<dim3((2 * DM) / 32, DM / 32), tb>>>(W_proj, WpTh, WpTl, 2 * DM, DM);
    for (int d2 = 0; d2 < 2; d2++) {
        wtrans_kernel<<<dim3(DM / 32, (4 * DM) / 32), tb>>>(W_in[d2],  WinTh + d2 * WIN_S, WinTl + d2 * WIN_S, DM, 4 * DM);
        wtrans_kernel<<<dim3(DI / 32, 128 / 32), tb>>>(W_x[d2],   WxTh  + d2 * WX_S,  WxTl  + d2 * WX_S,  DI, XDBW);
        wtrans_kernel<<<dim3(DTR / 32, DI / 32), tb>>>(W_dt[d2],  WdtTh + d2 * WDT_S, WdtTl + d2 * WDT_S, DTR, DI);
        wtrans_kernel<<<dim3(DI / 32, DM / 32), tb>>>(W_out[d2],  WoTh  + d2 * WO_S,  WoTl  + d2 * WO_S,  DI, DM);
    }
    pairify_kernel<<<(BT * DM + 255) / 256, 256>>>(x, xh, xl, BT * DM);

    // 1+2) fused: xg = x * gate(softplus(x@W_delta + b_delta) * exp(-alpha*u))
    tcgemm<<<ggrid(BT, DM, 1), 256, GEMM_SMEM>>>(
        xh, xl, WdTh, WdTl, fwd_out /*unused*/, b_delta, nullptr, xgh, xgl,
        x, u, alpha,
        BT, DM, DM, DM, DM, DM, 0, 0, 0, 0,
        F_BIAS | F_SP | F_GATE, 0);

    // 3) xz = xg @ W_in  (both dirs; bwd flips A rows)
    tcgemm<<<ggrid(BT, 4 * DM, 2), 256, GEMM_SMEM>>>(
        xgh, xgl, WinTh, WinTl, xz, nullptr, nullptr, nullptr, nullptr,
        nullptr, nullptr, nullptr,
        BT, 4 * DM, DM, 4 * DM, 0, 0, 0, WIN_S, XZ_S, 0, 0, F_FLIPA);

    // 4) conv + silu (both dirs)
    conv_kernel<<<dim3((BT * DI + 255) / 256, 1, 2), 256>>>(
        conv_w[0], conv_b[0], conv_w[1], conv_b[1]);

    // 5) xdb = xc @ W_x  (+pair of first 64 cols -> dt_lo pair), both dirs
    tcgemm<<<ggrid(BT, XDBW, 2), 256, GEMM_SMEM>>>(
        xch, xcl, WxTh, WxTl, xdb, nullptr, nullptr, dlh, dll,
        nullptr, nullptr, nullptr,
        BT, XDBW, DI, XDBW, DTR, DTR, XC_S, WX_S, XDB_S, DL_S, F_PAIR, F_PAIR);

    // 6) dt = softplus(dt_lo @ W_dt + b_dt), both dirs
    tcgemm<<<ggrid(BT, DI, 2), 256, GEMM_SMEM>>>(
        dlh, dll, WdtTh, WdtTl, dt, b_dt[0], b_dt[1], nullptr, nullptr,
        nullptr, nullptr, nullptr,
        BT, DI, DTR, DI, 0, 0, DL_S, WDT_S, XC_S, 0, F_BIAS | F_SP, F_BIAS | F_SP);

    // 7) selective scan -> y pair
    scan_kernel<<<dim3(DI / 64, BSZ, 2), 128>>>(A_log[0], Dp[0], A_log[1], Dp[1]);

    // 8) out_dir = y @ W_out (both dirs; bwd flips C rows); pairs into concat buf
    tcgemm<<<ggrid(BT, DM, 2), 256, GEMM_SMEM>>>(
        yh, yl, WoTh, WoTl, fwd_out, nullptr, nullptr, opch, opcl,
        nullptr, nullptr, nullptr,
        BT, DM, DI, DM, DM, 2 * DM, XC_S, WO_S, OP_S, DM,
        F_PAIR, F_PAIR | F_FLIPC);

    // 9) out = [fwd|bwd] @ W_proj + b_proj   (single K=2048 GEMM)
    tcgemm<<<ggrid(BT, DM, 1), 256, GEMM_SMEM>>>(
        opch, opcl, WpTh, WpTl, out, b_proj, nullptr, nullptr, nullptr,
        nullptr, nullptr, nullptr,
        BT, DM, 2 * DM, DM, 0, 0, 0, 0, 0, 0, F_BIAS, F_BIAS);
}